// round 14
// baseline (speedup 1.0000x reference)
#include <cuda_runtime.h>
#include <cuda_bf16.h>
#include <cstdint>

// Problem constants
#define B_  64
#define H_  128
#define W_  128
#define C_  3
#define KH_ 5
#define KW_ 5
#define N_  10
#define PAD_ 2
#define HW_ (H_ * W_)

#define RPB_   4     // output rows per block
#define FR_    8     // fill rows: h0-2 .. h0+5
#define SCRW_  404   // scratch row floats: col x at 8+3x+c, x in [-2,130]
#define NP_    66    // pair entries per (c,row): jj in [0,65], pair (v(2jj-2), v(2jj-1))

typedef unsigned long long u64;

__device__ __forceinline__ u64 pk2(float lo, float hi) {
    u64 r;
    asm("mov.b64 %0, {%1, %2};" : "=l"(r) : "f"(lo), "f"(hi));
    return r;
}
__device__ __forceinline__ u64 ffma2(u64 a, u64 b, u64 c) {
    u64 d;
    asm("fma.rn.f32x2 %0, %1, %2, %3;" : "=l"(d) : "l"(a), "l"(b), "l"(c));
    return d;
}
// (hi of a, lo of b) -- the odd-shift operand, built from already-loaded regs
__device__ __forceinline__ u64 shift1(u64 a, u64 b) {
    u64 r;
    asm("{\n\t"
        ".reg .f32 a0, a1, b0, b1;\n\t"
        "mov.b64 {a0, a1}, %1;\n\t"
        "mov.b64 {b0, b1}, %2;\n\t"
        "mov.b64 %0, {a1, b0};\n\t"
        "}" : "=l"(r) : "l"(a), "l"(b));
    return r;
}
__device__ __forceinline__ uint32_t smem_u32(const void* p) {
    uint32_t a;
    asm("{ .reg .u64 t; cvta.to.shared.u64 t, %1; cvt.u32.u64 %0, t; }" : "=r"(a) : "l"(p));
    return a;
}
__device__ __forceinline__ void cp_async16(uint32_t dst, const void* src) {
    asm volatile("cp.async.cg.shared.global [%0], [%1], 16;" :: "r"(dst), "l"(src) : "memory");
}

// Pixel-pair packing (R13) with SINGLE-phase pair array: even dw shifts are
// direct aligned LDS.64 E[p..p+2]; odd shifts derived via register re-pairing
// (shift1) from values already loaded. -100 LDS wavefronts/warp vs R13.
// E[jj] (stored) = (v(2jj-2), v(2jj-1)); tap dw needs cols (2p+dw-2, 2p+dw-1):
//   dw=0 -> E[p]   dw=2 -> E[p+1]   dw=4 -> E[p+2]
//   dw=1 -> (hi E[p],   lo E[p+1])
//   dw=3 -> (hi E[p+1], lo E[p+2])
extern "C" __global__ void __launch_bounds__(256, 3)
cdna_apply_kernel(const float* __restrict__ images,
                  const float* __restrict__ kernels,
                  float* __restrict__ out) {
    const int b  = blockIdx.y;          // batch
    const int h0 = blockIdx.x * RPB_;   // first of 4 output rows

    __shared__ __align__(16) float s_row[FR_][SCRW_];        // 12,928 B scratch
    __shared__ __align__(16) u64   s_e[C_][FR_][NP_];        // 12,672 B pair array
    __shared__ __align__(16) u64   s_kd[25][10];             // dup wts, 2,000 B

    const int tid = threadIdx.x;
    const float* img = images  + (size_t)b * (H_ * W_ * C_);
    const float* ker = kernels + b * (KH_ * KW_ * N_);

    // --- zero scratch (halos + out-of-range rows) ---
    {
        float4* p = reinterpret_cast<float4*>(&s_row[0][0]);
        for (int i = tid; i < (FR_ * SCRW_) / 4; i += 256)
            p[i] = make_float4(0.f, 0.f, 0.f, 0.f);
    }
    // duplicated weights
    if (tid < 250) {
        const int tap = tid / 10;
        const int n   = tid - tap * 10;
        const float v = ker[tid];
        s_kd[tap][n] = pk2(v, v);
    }
    __syncthreads();

    // --- interior fill via cp.async: 8 rows x 96 float4 ---
    for (int i = tid; i < FR_ * 96; i += 256) {
        const int r    = i / 96;
        const int col4 = i - r * 96;
        const int gr   = h0 - 2 + r;
        if ((unsigned)gr < (unsigned)H_) {
            const uint32_t dst = smem_u32(&s_row[r][8 + col4 * 4]);
            cp_async16(dst, img + gr * (W_ * C_) + col4 * 4);
        }
    }
    asm volatile("cp.async.commit_group;" ::: "memory");
    asm volatile("cp.async.wait_group 0;" ::: "memory");
    __syncthreads();

    // --- rearrange into single-phase pair array ---
    // col x lives at s_row[r][8+3x+c]; E[jj] = (v(2jj-2), v(2jj-1))
    for (int idx = tid; idx < C_ * FR_ * NP_; idx += 256) {
        const int c   = idx / (FR_ * NP_);
        const int rem = idx - c * (FR_ * NP_);
        const int r   = rem / NP_;
        const int jj  = rem - r * NP_;
        const float* sr = &s_row[r][8 + c];
        const float va = sr[3 * (2 * jj - 2)];
        const float vb = sr[3 * (2 * jj - 1)];
        s_e[c][r][jj] = pk2(va, vb);
    }
    __syncthreads();

    const int p  = tid & 63;    // pair index; pixels w0=2p, w0+1
    const int hr = tid >> 6;    // row within block (0..3)

    // acc[n][c]: f32x2 lanes = (pixel 2p, pixel 2p+1)
    u64 acc[N_][C_];
#pragma unroll
    for (int n = 0; n < N_; ++n)
#pragma unroll
        for (int c = 0; c < C_; ++c) acc[n][c] = 0ull;

#pragma unroll
    for (int dh = 0; dh < 5; ++dh) {
        // load E[p..p+2] for all 3 channels: 9 aligned conflict-free LDS.64
        const u64* eb = &s_e[0][hr + dh][p];
        u64 E[3][3];   // [c][k]
#pragma unroll
        for (int c = 0; c < C_; ++c) {
            const u64* ec = eb + c * (FR_ * NP_);
            E[c][0] = ec[0];
            E[c][1] = ec[1];
            E[c][2] = ec[2];
        }
#pragma unroll
        for (int dw = 0; dw < 5; ++dw) {
            u64 iv0, iv1, iv2;
            if ((dw & 1) == 0) {
                const int k = dw >> 1;
                iv0 = E[0][k]; iv1 = E[1][k]; iv2 = E[2][k];
            } else {
                const int k = dw >> 1;
                iv0 = shift1(E[0][k], E[0][k + 1]);
                iv1 = shift1(E[1][k], E[1][k + 1]);
                iv2 = shift1(E[2][k], E[2][k + 1]);
            }
            // duplicated weights: 5 broadcast LDS.128 (2 n each)
            const u64* kt = &s_kd[dh * 5 + dw][0];
            const ulonglong2 k01 = *reinterpret_cast<const ulonglong2*>(kt);
            const ulonglong2 k23 = *reinterpret_cast<const ulonglong2*>(kt + 2);
            const ulonglong2 k45 = *reinterpret_cast<const ulonglong2*>(kt + 4);
            const ulonglong2 k67 = *reinterpret_cast<const ulonglong2*>(kt + 6);
            const ulonglong2 k89 = *reinterpret_cast<const ulonglong2*>(kt + 8);

            acc[0][0] = ffma2(iv0, k01.x, acc[0][0]);
            acc[0][1] = ffma2(iv1, k01.x, acc[0][1]);
            acc[0][2] = ffma2(iv2, k01.x, acc[0][2]);
            acc[1][0] = ffma2(iv0, k01.y, acc[1][0]);
            acc[1][1] = ffma2(iv1, k01.y, acc[1][1]);
            acc[1][2] = ffma2(iv2, k01.y, acc[1][2]);
            acc[2][0] = ffma2(iv0, k23.x, acc[2][0]);
            acc[2][1] = ffma2(iv1, k23.x, acc[2][1]);
            acc[2][2] = ffma2(iv2, k23.x, acc[2][2]);
            acc[3][0] = ffma2(iv0, k23.y, acc[3][0]);
            acc[3][1] = ffma2(iv1, k23.y, acc[3][1]);
            acc[3][2] = ffma2(iv2, k23.y, acc[3][2]);
            acc[4][0] = ffma2(iv0, k45.x, acc[4][0]);
            acc[4][1] = ffma2(iv1, k45.x, acc[4][1]);
            acc[4][2] = ffma2(iv2, k45.x, acc[4][2]);
            acc[5][0] = ffma2(iv0, k45.y, acc[5][0]);
            acc[5][1] = ffma2(iv1, k45.y, acc[5][1]);
            acc[5][2] = ffma2(iv2, k45.y, acc[5][2]);
            acc[6][0] = ffma2(iv0, k67.x, acc[6][0]);
            acc[6][1] = ffma2(iv1, k67.x, acc[6][1]);
            acc[6][2] = ffma2(iv2, k67.x, acc[6][2]);
            acc[7][0] = ffma2(iv0, k67.y, acc[7][0]);
            acc[7][1] = ffma2(iv1, k67.y, acc[7][1]);
            acc[7][2] = ffma2(iv2, k67.y, acc[7][2]);
            acc[8][0] = ffma2(iv0, k89.x, acc[8][0]);
            acc[8][1] = ffma2(iv1, k89.x, acc[8][1]);
            acc[8][2] = ffma2(iv2, k89.x, acc[8][2]);
            acc[9][0] = ffma2(iv0, k89.y, acc[9][0]);
            acc[9][1] = ffma2(iv1, k89.y, acc[9][1]);
            acc[9][2] = ffma2(iv2, k89.y, acc[9][2]);
        }
    }

    // --- store: out[n][b][c][h][w0..w0+1] -> STG.64, coalesced ---
    const int hpix = h0 + hr;
    const int w0   = 2 * p;
    char* o0 = reinterpret_cast<char*>(out)
             + (((size_t)b * C_) * HW_ + hpix * W_ + w0) * sizeof(float);
#pragma unroll
    for (int n = 0; n < N_; ++n) {
        char* on = o0 + (size_t)n * (B_ * C_ * HW_) * sizeof(float);
#pragma unroll
        for (int c = 0; c < C_; ++c)
            *reinterpret_cast<u64*>(on + (size_t)c * HW_ * sizeof(float)) = acc[n][c];
    }
}

extern "C" void kernel_launch(void* const* d_in, const int* in_sizes, int n_in,
                              void* d_out, int out_size) {
    const float* images  = (const float*)d_in[0];  // [64,128,128,3]
    const float* kernels = (const float*)d_in[1];  // [64,5,5,10]
    float* out = (float*)d_out;                    // [10,64,3,128,128]
    (void)in_sizes; (void)n_in; (void)out_size;

    dim3 grid(H_ / RPB_, B_);   // 32 x 64 blocks
    dim3 block(256);
    cdna_apply_kernel<<<grid, block>>>(images, kernels, out);
}

// round 15
// speedup vs baseline: 1.8195x; 1.8195x over previous
#include <cuda_runtime.h>
#include <cuda_bf16.h>
#include <cstdint>

// Problem constants
#define B_  64
#define H_  128
#define W_  128
#define C_  3
#define KH_ 5
#define KW_ 5
#define N_  10
#define PAD_ 2
#define HW_ (H_ * W_)

#define RPB_ 4      // output rows per block
#define FR_  8      // pair-array rows: h0-2 .. h0+5
#define NP_  66     // pair entries per (c,row)

typedef unsigned long long u64;

__device__ __forceinline__ u64 pk2(float lo, float hi) {
    u64 r;
    asm("mov.b64 %0, {%1, %2};" : "=l"(r) : "f"(lo), "f"(hi));
    return r;
}
__device__ __forceinline__ u64 ffma2(u64 a, u64 b, u64 c) {
    u64 d;
    asm("fma.rn.f32x2 %0, %1, %2, %3;" : "=l"(d) : "l"(a), "l"(b), "l"(c));
    return d;
}

// R13 mainloop (pixel-pair f32x2, dual-phase pair arrays, dup weights) with a
// single-pass prologue: pair arrays built DIRECTLY from gmem via predicated
// LDG (halos from predicates) -> no scratch tile, no zero-fill, one sync.
// Tap mapping (output pair (2p,2p+1), tap dw -> cols (2p+dw-2, 2p+dw-1)):
//   phase = dw&1, j = p + (dw>>1).
extern "C" __global__ void __launch_bounds__(256, 3)
cdna_apply_kernel(const float* __restrict__ images,
                  const float* __restrict__ kernels,
                  float* __restrict__ out) {
    const int b  = blockIdx.y;          // batch
    const int h0 = blockIdx.x * RPB_;   // first of 4 output rows

    __shared__ __align__(16) u64 s_p0[C_][FR_][NP_];   // 12,672 B
    __shared__ __align__(16) u64 s_p1[C_][FR_][NP_];   // 12,672 B
    __shared__ __align__(16) u64 s_kd[25][10];         // dup weights, 2,000 B

    const int tid = threadIdx.x;
    const float* img = images  + (size_t)b * (H_ * W_ * C_);
    const float* ker = kernels + b * (KH_ * KW_ * N_);

    // --- duplicated weights ---
    if (tid < 250) {
        const int tap = tid / 10;
        const int n   = tid - tap * 10;
        const float v = ker[tid];
        s_kd[tap][n] = pk2(v, v);
    }

    // --- build pair arrays straight from gmem (each entry written once) ---
    // entry (c,r,jj): cols x0=2jj-2, x1=2jj-1, x2=2jj; row gr=h0-2+r.
    // p0[jj]=(v(x0),v(x1)); p1[jj]=(v(x1),v(x2)). OOB -> 0 via predicates.
    for (int idx = tid; idx < C_ * FR_ * NP_; idx += 256) {
        const int c   = idx / (FR_ * NP_);
        const int rem = idx - c * (FR_ * NP_);
        const int r   = rem / NP_;
        const int jj  = rem - r * NP_;
        const int gr  = h0 - 2 + r;
        const bool rv = (unsigned)gr < (unsigned)H_;
        const int x0  = 2 * jj - 2;
        const float* rp = img + (gr * W_) * C_ + c;   // + 3*x indexes col x
        float va = 0.f, vb = 0.f, vc = 0.f;
        if (rv) {
            if ((unsigned)x0 < (unsigned)W_)       va = rp[3 * x0];
            if ((unsigned)(x0 + 1) < (unsigned)W_) vb = rp[3 * x0 + 3];
            if ((unsigned)(x0 + 2) < (unsigned)W_) vc = rp[3 * x0 + 6];
        }
        s_p0[c][r][jj] = pk2(va, vb);
        s_p1[c][r][jj] = pk2(vb, vc);
    }
    __syncthreads();

    const int p  = tid & 63;    // pair index; pixels w0=2p, w0+1
    const int hr = tid >> 6;    // row within block (0..3)

    // acc[n][c]: f32x2 lanes = (pixel 2p, pixel 2p+1)
    u64 acc[N_][C_];
#pragma unroll
    for (int n = 0; n < N_; ++n)
#pragma unroll
        for (int c = 0; c < C_; ++c) acc[n][c] = 0ull;

#pragma unroll
    for (int dh = 0; dh < 5; ++dh) {
#pragma unroll
        for (int dw = 0; dw < 5; ++dw) {
            // iv per channel: ONE aligned conflict-free LDS.64
            const int j = p + (dw >> 1);           // p, p, p+1, p+1, p+2
            const u64* ph = (dw & 1) ? &s_p1[0][0][0] : &s_p0[0][0][0];
            const int ro = (hr + dh) * NP_ + j;
            const u64 iv0 = ph[0 * (FR_ * NP_) + ro];
            const u64 iv1 = ph[1 * (FR_ * NP_) + ro];
            const u64 iv2 = ph[2 * (FR_ * NP_) + ro];

            // duplicated weights: 5 broadcast LDS.128 (2 n each)
            const u64* kt = &s_kd[dh * 5 + dw][0];
            const ulonglong2 k01 = *reinterpret_cast<const ulonglong2*>(kt);
            const ulonglong2 k23 = *reinterpret_cast<const ulonglong2*>(kt + 2);
            const ulonglong2 k45 = *reinterpret_cast<const ulonglong2*>(kt + 4);
            const ulonglong2 k67 = *reinterpret_cast<const ulonglong2*>(kt + 6);
            const ulonglong2 k89 = *reinterpret_cast<const ulonglong2*>(kt + 8);

            acc[0][0] = ffma2(iv0, k01.x, acc[0][0]);
            acc[0][1] = ffma2(iv1, k01.x, acc[0][1]);
            acc[0][2] = ffma2(iv2, k01.x, acc[0][2]);
            acc[1][0] = ffma2(iv0, k01.y, acc[1][0]);
            acc[1][1] = ffma2(iv1, k01.y, acc[1][1]);
            acc[1][2] = ffma2(iv2, k01.y, acc[1][2]);
            acc[2][0] = ffma2(iv0, k23.x, acc[2][0]);
            acc[2][1] = ffma2(iv1, k23.x, acc[2][1]);
            acc[2][2] = ffma2(iv2, k23.x, acc[2][2]);
            acc[3][0] = ffma2(iv0, k23.y, acc[3][0]);
            acc[3][1] = ffma2(iv1, k23.y, acc[3][1]);
            acc[3][2] = ffma2(iv2, k23.y, acc[3][2]);
            acc[4][0] = ffma2(iv0, k45.x, acc[4][0]);
            acc[4][1] = ffma2(iv1, k45.x, acc[4][1]);
            acc[4][2] = ffma2(iv2, k45.x, acc[4][2]);
            acc[5][0] = ffma2(iv0, k45.y, acc[5][0]);
            acc[5][1] = ffma2(iv1, k45.y, acc[5][1]);
            acc[5][2] = ffma2(iv2, k45.y, acc[5][2]);
            acc[6][0] = ffma2(iv0, k67.x, acc[6][0]);
            acc[6][1] = ffma2(iv1, k67.x, acc[6][1]);
            acc[6][2] = ffma2(iv2, k67.x, acc[6][2]);
            acc[7][0] = ffma2(iv0, k67.y, acc[7][0]);
            acc[7][1] = ffma2(iv1, k67.y, acc[7][1]);
            acc[7][2] = ffma2(iv2, k67.y, acc[7][2]);
            acc[8][0] = ffma2(iv0, k89.x, acc[8][0]);
            acc[8][1] = ffma2(iv1, k89.x, acc[8][1]);
            acc[8][2] = ffma2(iv2, k89.x, acc[8][2]);
            acc[9][0] = ffma2(iv0, k89.y, acc[9][0]);
            acc[9][1] = ffma2(iv1, k89.y, acc[9][1]);
            acc[9][2] = ffma2(iv2, k89.y, acc[9][2]);
        }
    }

    // --- store: out[n][b][c][h][w0..w0+1] -> STG.64, coalesced ---
    const int hpix = h0 + hr;
    const int w0   = 2 * p;
    char* o0 = reinterpret_cast<char*>(out)
             + (((size_t)b * C_) * HW_ + hpix * W_ + w0) * sizeof(float);
#pragma unroll
    for (int n = 0; n < N_; ++n) {
        char* on = o0 + (size_t)n * (B_ * C_ * HW_) * sizeof(float);
#pragma unroll
        for (int c = 0; c < C_; ++c)
            *reinterpret_cast<u64*>(on + (size_t)c * HW_ * sizeof(float)) = acc[n][c];
    }
}

extern "C" void kernel_launch(void* const* d_in, const int* in_sizes, int n_in,
                              void* d_out, int out_size) {
    const float* images  = (const float*)d_in[0];  // [64,128,128,3]
    const float* kernels = (const float*)d_in[1];  // [64,5,5,10]
    float* out = (float*)d_out;                    // [10,64,3,128,128]
    (void)in_sizes; (void)n_in; (void)out_size;

    dim3 grid(H_ / RPB_, B_);   // 32 x 64 blocks
    dim3 block(256);
    cdna_apply_kernel<<<grid, block>>>(images, kernels, out);
}